// round 1
// baseline (speedup 1.0000x reference)
#include <cuda_runtime.h>
#include <cuda_bf16.h>

// ⟨Z_0⟩ after RY·RX on every qubit + CNOT chain reduces analytically to a
// function of only the qubit-0 gate (CNOTs preserve qubit-0 bit; gates on
// qubits 1..15 are block-unitary and preserve per-block norms):
//
//   A = ||u||^2 - ||v||^2,  S = sum(u * conj(v))   (u = top half, v = bottom half)
//   <Z_0> = cos^2(t0) * A - 2 sin(t0) * (Re S + cos(t0) * Im S)
//
// => three fused reductions over 32768 complex pairs per batch row.

#ifndef QN
#define QN 16
#endif
static constexpr int D      = 1 << QN;     // 65536
static constexpr int HALF   = D >> 1;      // 32768 floats per half-row per array
static constexpr int HALF4  = HALF >> 2;   // 8192 float4 per half-row per array
static constexpr int NTHREADS = 1024;

__inline__ __device__ float warp_sum(float v) {
    #pragma unroll
    for (int o = 16; o > 0; o >>= 1)
        v += __shfl_down_sync(0xffffffffu, v, o);
    return v;
}

__global__ __launch_bounds__(NTHREADS, 1)
void zexp_kernel(const float* __restrict__ re,
                 const float* __restrict__ im,
                 const float* __restrict__ thetas,
                 float* __restrict__ out)
{
    const int row = blockIdx.x;
    const size_t base = (size_t)row * D;

    const float4* __restrict__ ru = (const float4*)(re + base);          // u real
    const float4* __restrict__ rv = (const float4*)(re + base + HALF);   // v real
    const float4* __restrict__ iu = (const float4*)(im + base);          // u imag
    const float4* __restrict__ iv = (const float4*)(im + base + HALF);   // v imag

    float A = 0.f, P = 0.f, Q = 0.f;

    // 8192 float4 / 1024 threads = 8 iterations; fully unrolled so all 32
    // independent LDG.128 per thread are front-batched (MLP >> 4 hides DRAM).
    #pragma unroll
    for (int k = 0; k < HALF4 / NTHREADS; ++k) {
        const int idx = threadIdx.x + k * NTHREADS;
        const float4 a = ru[idx];   // u_r
        const float4 b = rv[idx];   // v_r
        const float4 c = iu[idx];   // u_i
        const float4 d = iv[idx];   // v_i

        A += (a.x*a.x + c.x*c.x) - (b.x*b.x + d.x*d.x);
        A += (a.y*a.y + c.y*c.y) - (b.y*b.y + d.y*d.y);
        A += (a.z*a.z + c.z*c.z) - (b.z*b.z + d.z*d.z);
        A += (a.w*a.w + c.w*c.w) - (b.w*b.w + d.w*d.w);

        P += a.x*b.x + c.x*d.x;
        P += a.y*b.y + c.y*d.y;
        P += a.z*b.z + c.z*d.z;
        P += a.w*b.w + c.w*d.w;

        Q += c.x*b.x - a.x*d.x;
        Q += c.y*b.y - a.y*d.y;
        Q += c.z*b.z - a.z*d.z;
        Q += c.w*b.w - a.w*d.w;
    }

    // intra-warp reduce
    A = warp_sum(A);
    P = warp_sum(P);
    Q = warp_sum(Q);

    __shared__ float sA[NTHREADS / 32];
    __shared__ float sP[NTHREADS / 32];
    __shared__ float sQ[NTHREADS / 32];

    const int lane = threadIdx.x & 31;
    const int wid  = threadIdx.x >> 5;
    if (lane == 0) { sA[wid] = A; sP[wid] = P; sQ[wid] = Q; }
    __syncthreads();

    if (wid == 0) {
        A = (lane < NTHREADS / 32) ? sA[lane] : 0.f;
        P = (lane < NTHREADS / 32) ? sP[lane] : 0.f;
        Q = (lane < NTHREADS / 32) ? sQ[lane] : 0.f;
        A = warp_sum(A);
        P = warp_sum(P);
        Q = warp_sum(Q);
        if (lane == 0) {
            const float t  = thetas[0];
            const float ct = cosf(t);
            const float st = sinf(t);
            out[row] = ct * ct * A - 2.f * st * (P + ct * Q);
        }
    }
}

extern "C" void kernel_launch(void* const* d_in, const int* in_sizes, int n_in,
                              void* d_out, int out_size)
{
    const float* re     = (const float*)d_in[0];  // states_re (128, 65536)
    const float* im     = (const float*)d_in[1];  // states_im (128, 65536)
    const float* thetas = (const float*)d_in[2];  // (16,)
    float* out = (float*)d_out;                   // (128,)

    const int B = in_sizes[0] / D;                // 128
    zexp_kernel<<<B, NTHREADS>>>(re, im, thetas, out);
}